// round 11
// baseline (speedup 1.0000x reference)
#include <cuda_runtime.h>
#include <cuda_bf16.h>
#include <cstdint>
#include <cstddef>

#define MROWS (512*512)
#define NTILES 2048
#define GRID 296
#define NTH 128

// ---------------- smem layout (bytes) ----------------
// SB1: stage-1 B fragments uint32[3 f][8 j][4 s][32 lane][4 q]  q={hi0,hi1,lo0,lo1}
// SB2: stage-2 B fragments uint32[3][4][4][32][4]
// B1S/B2S: biases. U: unit vectors [128][4] (single buffer; tile-end barrier).
#define OFF_SB1 0u
#define OFF_SB2 49152u
#define OFF_B1  73728u
#define OFF_B2  74496u
#define OFF_U   74880u
#define SMEM_BYTES 76928u   // 75.125 KB -> 3 CTAs/SM

struct Params {
  const float* x0;
  const float* x1;
  const float* rij;
  const float* w[12];   // f0: w1,b1,w2,b2 ; f10: ... ; f11: ...
  float* out;
};

__device__ __forceinline__ void mma16816(float (&c)[4], const uint32_t (&a)[4],
                                         uint32_t b0, uint32_t b1) {
  asm volatile(
      "mma.sync.aligned.m16n8k16.row.col.f32.bf16.bf16.f32 "
      "{%0,%1,%2,%3}, {%4,%5,%6,%7}, {%8,%9}, {%0,%1,%2,%3};"
      : "+f"(c[0]), "+f"(c[1]), "+f"(c[2]), "+f"(c[3])
      : "r"(a[0]), "r"(a[1]), "r"(a[2]), "r"(a[3]), "r"(b0), "r"(b1));
}

__device__ __forceinline__ uint32_t pack_split(float vx, float vy, uint32_t& lo) {
  __nv_bfloat162 h = __float22bfloat162_rn(make_float2(vx, vy));
  float2 hf = __bfloat1622float2(h);
  __nv_bfloat162 l = __float22bfloat162_rn(make_float2(vx - hf.x, vy - hf.y));
  lo = *reinterpret_cast<uint32_t*>(&l);
  return *reinterpret_cast<uint32_t*>(&h);
}

__device__ __forceinline__ __nv_bfloat16 bf_part(float v, int h) {
  __nv_bfloat16 hi = __float2bfloat16_rn(v);
  if (h == 0) return hi;
  return __float2bfloat16_rn(v - __bfloat162float(hi));
}

// ---- proven scatter epilogues ----
__device__ __forceinline__ void epi_plain(const float (&C2)[4][4], int g, int t,
                                          float* __restrict__ outp, int rowbase) {
  float* r0p = outp + (size_t)(rowbase + g) * 32;
  float* r1p = outp + (size_t)(rowbase + g + 8) * 32;
#pragma unroll
  for (int j2 = 0; j2 < 4; j2++) {
    int col = 8 * j2 + 2 * t;
    *(float2*)(r0p + col) = make_float2(C2[j2][0], C2[j2][1]);
    *(float2*)(r1p + col) = make_float2(C2[j2][2], C2[j2][3]);
  }
}

__device__ __forceinline__ void epi_vec(const float (&C2)[4][4],
                                        const float* __restrict__ ub,
                                        int ro, int g, int t,
                                        float* __restrict__ outp, int rowbase) {
  const float* u0p = ub + ro * 4;
  const float* u1p = ub + (ro + 8) * 4;
  float ua0 = u0p[0], ua1 = u0p[1], ua2 = u0p[2];
  float ub0 = u1p[0], ub1 = u1p[1], ub2 = u1p[2];
  float* r0p = outp + (size_t)(rowbase + g) * 96;
  float* r1p = outp + (size_t)(rowbase + g + 8) * 96;
#pragma unroll
  for (int j2 = 0; j2 < 4; j2++) {
    int col3 = (8 * j2 + 2 * t) * 3;   // byte off 96*j2+24*t -> 8-aligned
    float v0 = C2[j2][0], v1 = C2[j2][1];
    *(float2*)(r0p + col3 + 0) = make_float2(v0 * ua0, v0 * ua1);
    *(float2*)(r0p + col3 + 2) = make_float2(v0 * ua2, v1 * ua0);
    *(float2*)(r0p + col3 + 4) = make_float2(v1 * ua1, v1 * ua2);
    float w0 = C2[j2][2], w1 = C2[j2][3];
    *(float2*)(r1p + col3 + 0) = make_float2(w0 * ub0, w0 * ub1);
    *(float2*)(r1p + col3 + 2) = make_float2(w0 * ub2, w1 * ub0);
    *(float2*)(r1p + col3 + 4) = make_float2(w1 * ub1, w1 * ub2);
  }
}

// bias+relu -> stage-2 A frags -> GEMM2 -> bias -> epilogue, for ONE slice.
__device__ __forceinline__ void stage2_epi(
    float (&C1)[8][4], int f,
    const uint32_t* __restrict__ sb2l4,
    const float* __restrict__ B1s, const float* __restrict__ B2s,
    const float* __restrict__ ub, int ro, int g, int t,
    float* __restrict__ outp, int rowbase, bool vec) {
  const float* b1f = B1s + f * 64;
#pragma unroll
  for (int j = 0; j < 8; j++) {
    float2 b = *(const float2*)(b1f + 8 * j + 2 * t);
    C1[j][0] = fmaxf(C1[j][0] + b.x, 0.f);
    C1[j][1] = fmaxf(C1[j][1] + b.y, 0.f);
    C1[j][2] = fmaxf(C1[j][2] + b.x, 0.f);
    C1[j][3] = fmaxf(C1[j][3] + b.y, 0.f);
  }
  uint32_t A2h[4][4], A2l[4][4];
#pragma unroll
  for (int s2 = 0; s2 < 4; s2++) {
    A2h[s2][0] = pack_split(C1[2 * s2][0],     C1[2 * s2][1],     A2l[s2][0]);
    A2h[s2][1] = pack_split(C1[2 * s2][2],     C1[2 * s2][3],     A2l[s2][1]);
    A2h[s2][2] = pack_split(C1[2 * s2 + 1][0], C1[2 * s2 + 1][1], A2l[s2][2]);
    A2h[s2][3] = pack_split(C1[2 * s2 + 1][2], C1[2 * s2 + 1][3], A2l[s2][3]);
  }
  float C2[4][4];
#pragma unroll
  for (int j = 0; j < 4; j++)
#pragma unroll
    for (int e = 0; e < 4; e++) C2[j][e] = 0.f;
#pragma unroll
  for (int j2 = 0; j2 < 4; j2++) {
#pragma unroll
    for (int s2 = 0; s2 < 4; s2++) {
      uint4 bb = *(const uint4*)(sb2l4 + ((f * 4 + j2) * 4 + s2) * 128);
      mma16816(C2[j2], A2h[s2], bb.x, bb.y);
      mma16816(C2[j2], A2l[s2], bb.x, bb.y);
      mma16816(C2[j2], A2h[s2], bb.z, bb.w);
    }
  }
  const float* b2f = B2s + f * 32;
#pragma unroll
  for (int j2 = 0; j2 < 4; j2++) {
    float2 b = *(const float2*)(b2f + 8 * j2 + 2 * t);
    C2[j2][0] += b.x; C2[j2][1] += b.y;
    C2[j2][2] += b.x; C2[j2][3] += b.y;
  }
  if (vec) epi_vec(C2, ub, ro, g, t, outp, rowbase);
  else     epi_plain(C2, g, t, outp, rowbase);
}

// dual-slice stage 1 (shared B loads, 2x ILP) -> sequential per-slice stage 2.
__device__ __forceinline__ void run_pair(
    const uint32_t (&Ah0)[4][4], const uint32_t (&Al0)[4][4],
    const uint32_t (&Ah1)[4][4], const uint32_t (&Al1)[4][4], int f,
    const uint32_t* __restrict__ sb1l4, const uint32_t* __restrict__ sb2l4,
    const float* __restrict__ B1s, const float* __restrict__ B2s,
    const float* __restrict__ ub, int ro, int g, int t,
    float* __restrict__ outp, int rowbase, bool vec) {
  float C1a[8][4], C1b[8][4];
#pragma unroll
  for (int j = 0; j < 8; j++)
#pragma unroll
    for (int e = 0; e < 4; e++) { C1a[j][e] = 0.f; C1b[j][e] = 0.f; }
#pragma unroll
  for (int j = 0; j < 8; j++) {
#pragma unroll
    for (int s = 0; s < 4; s++) {
      uint4 bb = *(const uint4*)(sb1l4 + ((f * 8 + j) * 4 + s) * 128);
      mma16816(C1a[j], Ah0[s], bb.x, bb.y);
      mma16816(C1b[j], Ah1[s], bb.x, bb.y);
      mma16816(C1a[j], Al0[s], bb.x, bb.y);
      mma16816(C1b[j], Al1[s], bb.x, bb.y);
      mma16816(C1a[j], Ah0[s], bb.z, bb.w);
      mma16816(C1b[j], Ah1[s], bb.z, bb.w);
    }
  }
  stage2_epi(C1a, f, sb2l4, B1s, B2s, ub, ro,      g, t, outp, rowbase,      vec);
  stage2_epi(C1b, f, sb2l4, B1s, B2s, ub, ro + 64, g, t, outp, rowbase + 64, vec);
}

// load x rows into A fragments (hi/lo bf16) for one 16-row slice
__device__ __forceinline__ void load_xfrags(const float* __restrict__ x, int row0,
                                            int ro, int t,
                                            uint32_t (&Ah)[4][4], uint32_t (&Al)[4][4]) {
  const float* base = x + (size_t)(row0 + ro) * 64 + 2 * t;
#pragma unroll
  for (int s = 0; s < 4; s++) {
    const float* bs = base + 16 * s;
    float2 v0 = __ldg((const float2*)(bs));
    float2 v1 = __ldg((const float2*)(bs + 8 * 64));
    float2 v2 = __ldg((const float2*)(bs + 8));
    float2 v3 = __ldg((const float2*)(bs + 8 * 64 + 8));
    Ah[s][0] = pack_split(v0.x, v0.y, Al[s][0]);
    Ah[s][1] = pack_split(v1.x, v1.y, Al[s][1]);
    Ah[s][2] = pack_split(v2.x, v2.y, Al[s][2]);
    Ah[s][3] = pack_split(v3.x, v3.y, Al[s][3]);
  }
}

// 3 CTAs/SM: 12 warps/SM (was 8). Reg cap 170 -> accept mild spills in
// exchange for +50% latency hiding.
__global__ void __launch_bounds__(NTH, 3) conv_mma(Params p) {
  extern __shared__ char sm[];
  uint32_t* SB1 = (uint32_t*)(sm + OFF_SB1);
  uint32_t* SB2 = (uint32_t*)(sm + OFF_SB2);
  float* B1s = (float*)(sm + OFF_B1);
  float* B2s = (float*)(sm + OFF_B2);
  float* U   = (float*)(sm + OFF_U);

  const int tid = threadIdx.x;

  // ---- one-time: build B fragments, hi/lo interleaved per lane (LDS.128) ----
  // filter order: 0=f0 (w[0..3]), 1=f11 (w[8..11]), 2=f10 (w[4..7])
  for (int idx = tid; idx < 12288; idx += NTH) {
    int i = idx;
    int q = i & 3; i >>= 2;
    int lane = i & 31; i >>= 5;
    int s = i & 3; i >>= 2;
    int j = i & 7; i >>= 3;
    int f = i;
    int half = q >> 1, r = q & 1;
    int g = lane >> 2, t = lane & 3;
    int n = 8 * j + g;
    int kb = 16 * s + 2 * t + 8 * r;
    const float* w1 = (f == 0) ? p.w[0] : (f == 1) ? p.w[8] : p.w[4];
    float v0 = __ldg(w1 + kb * 64 + n);
    float v1 = __ldg(w1 + (kb + 1) * 64 + n);
    __nv_bfloat162 pk;
    pk.x = bf_part(v0, half);
    pk.y = bf_part(v1, half);
    SB1[idx] = *reinterpret_cast<uint32_t*>(&pk);
  }
  for (int idx = tid; idx < 6144; idx += NTH) {
    int i = idx;
    int q = i & 3; i >>= 2;
    int lane = i & 31; i >>= 5;
    int s = i & 3; i >>= 2;
    int j = i & 3; i >>= 2;
    int f = i;
    int half = q >> 1, r = q & 1;
    int g = lane >> 2, t = lane & 3;
    int n = 8 * j + g;
    int kb = 16 * s + 2 * t + 8 * r;
    const float* w2 = (f == 0) ? p.w[2] : (f == 1) ? p.w[10] : p.w[6];
    float v0 = __ldg(w2 + kb * 32 + n);
    float v1 = __ldg(w2 + (kb + 1) * 32 + n);
    __nv_bfloat162 pk;
    pk.x = bf_part(v0, half);
    pk.y = bf_part(v1, half);
    SB2[idx] = *reinterpret_cast<uint32_t*>(&pk);
  }
  for (int n = tid; n < 192; n += NTH) {
    const float* b1 = (n < 64) ? p.w[1] : (n < 128) ? p.w[9] : p.w[5];
    B1s[n] = __ldg(b1 + (n & 63));
  }
  for (int n = tid; n < 96; n += NTH) {
    const float* b2 = (n < 32) ? p.w[3] : (n < 64) ? p.w[11] : p.w[7];
    B2s[n] = __ldg(b2 + (n & 31));
  }
  __syncthreads();

  const int w = tid >> 5, lane = tid & 31;
  const int g = lane >> 2, t = lane & 3;
  const int ro = w * 16 + g;            // slice a; slice b = ro + 64
  const uint32_t* sb1l4 = SB1 + lane * 4;
  const uint32_t* sb2l4 = SB2 + lane * 4;

  float* const o0a = p.out;
  float* const o0b = p.out + (size_t)32 * MROWS;
  float* const o1a = p.out + (size_t)64 * MROWS;
  float* const o1b = p.out + (size_t)160 * MROWS;
  float* const o1c = p.out + (size_t)256 * MROWS;

  for (int tile = blockIdx.x; tile < NTILES; tile += GRID) {
    const int row0 = tile << 7;
    {
      const float* rp = p.rij + (size_t)(row0 + tid) * 3;
      float r0 = rp[0], r1 = rp[1], r2 = rp[2];
      float d2 = r0 * r0 + r1 * r1 + r2 * r2;
      float dij = sqrtf(d2);
      float nrm = sqrtf(fmaxf(d2, 1e-8f));
      float* uu = U + tid * 4;
      if (dij < 1e-8f) { uu[0] = 0.f; uu[1] = 0.f; uu[2] = 0.f; }
      else { uu[0] = r0 / nrm; uu[1] = r1 / nrm; uu[2] = r2 / nrm; }
    }
    __syncthreads();

    uint32_t Ah0[4][4], Al0[4][4], Ah1[4][4], Al1[4][4];
    const int rowbase = row0 + w * 16;

    // x0: f0 -> out0_a (plain), f11 -> out1_a (vec)
    load_xfrags(p.x0, row0, ro, t, Ah0, Al0);
    load_xfrags(p.x0, row0, ro + 64, t, Ah1, Al1);
    run_pair(Ah0, Al0, Ah1, Al1, 0, sb1l4, sb2l4, B1s, B2s, U, ro, g, t, o0a, rowbase, false);
    run_pair(Ah0, Al0, Ah1, Al1, 1, sb1l4, sb2l4, B1s, B2s, U, ro, g, t, o1a, rowbase, true);

    // x1: f0 -> out0_b (plain), f10 -> out1_b (vec), f11 -> out1_c (vec)
    load_xfrags(p.x1, row0, ro, t, Ah0, Al0);
    load_xfrags(p.x1, row0, ro + 64, t, Ah1, Al1);
    run_pair(Ah0, Al0, Ah1, Al1, 0, sb1l4, sb2l4, B1s, B2s, U, ro, g, t, o0b, rowbase, false);
    run_pair(Ah0, Al0, Ah1, Al1, 2, sb1l4, sb2l4, B1s, B2s, U, ro, g, t, o1b, rowbase, true);
    run_pair(Ah0, Al0, Ah1, Al1, 1, sb1l4, sb2l4, B1s, B2s, U, ro, g, t, o1c, rowbase, true);

    // single-buffer U: all warps must finish epi_vec reads before the next
    // tile's U write.
    __syncthreads();
  }
}

extern "C" void kernel_launch(void* const* d_in, const int* in_sizes, int n_in,
                              void* d_out, int out_size) {
  Params p;
  p.x0  = (const float*)d_in[0];
  p.x1  = (const float*)d_in[1];
  // d_in[2] = rbf: unused by the reference computation
  p.rij = (const float*)d_in[3];
  for (int i = 0; i < 12; i++) p.w[i] = (const float*)d_in[4 + i];
  p.out = (float*)d_out;

  cudaFuncSetAttribute(conv_mma, cudaFuncAttributeMaxDynamicSharedMemorySize, SMEM_BYTES);
  conv_mma<<<GRID, NTH, SMEM_BYTES>>>(p);
}